// round 6
// baseline (speedup 1.0000x reference)
#include <cuda_runtime.h>
#include <math.h>

#define N_TOK 2048*2
#define D_DIM 2048
#define N_EXP 8
#define TOPK  2
#define CAP   512
#define PITCH 1028                 // padded smem row (floats)
#define DISP_BYTES ((size_t)N_TOK * N_EXP * CAP * 4)   // 64 MB

__device__ int g_choice[N_TOK * TOPK];

// ---------------------------------------------------------------------------
// GEMM: logits = x @ W, top-2, softmax. 2 tokens/warp, 8 warps/block,
// 256 blocks. launch_bounds(256,3) -> <=83 regs -> 3 blocks/SM (24 warps),
// fixing the MLP/occupancy limit that pinned R2 at 2.2 TB/s.
// ---------------------------------------------------------------------------
__global__ __launch_bounds__(256, 3) void k_logits_topk(
        const float* __restrict__ x,
        const float* __restrict__ W,
        float* __restrict__ out) {
    __shared__ float wt[N_EXP * PITCH];   // 32.9 KB

    int tid  = threadIdx.x;
    int lane = tid & 31;
    int wrp  = tid >> 5;
    int t0   = (blockIdx.x * 8 + wrp) * 2;

    const float4* x4 = reinterpret_cast<const float4*>(x);
    float acc0[N_EXP] = {0,0,0,0,0,0,0,0};
    float acc1[N_EXP] = {0,0,0,0,0,0,0,0};

    for (int p = 0; p < 2; p++) {
        // stage W[p*1024 .. +1024) transposed: wt[e][d]
        for (int idx = tid; idx < 1024 * N_EXP; idx += 256) {
            int dl = idx >> 3;
            int e  = idx & 7;
            wt[e * PITCH + dl] = W[(p * 1024 + dl) * N_EXP + e];
        }
        __syncthreads();

        #pragma unroll 2
        for (int i = 0; i < 8; i++) {
            int j = i * 32 + lane;      // float4 idx within phase [0,256)
            float4 xv0 = __ldcs(&x4[(size_t)t0       * (D_DIM/4) + p * 256 + j]);
            float4 xv1 = __ldcs(&x4[(size_t)(t0 + 1) * (D_DIM/4) + p * 256 + j]);
            #pragma unroll
            for (int e = 0; e < N_EXP; e++) {
                float4 w = *reinterpret_cast<const float4*>(&wt[e * PITCH + j * 4]);
                acc0[e] += xv0.x * w.x + xv0.y * w.y + xv0.z * w.z + xv0.w * w.w;
                acc1[e] += xv1.x * w.x + xv1.y * w.y + xv1.z * w.z + xv1.w * w.w;
            }
        }
        __syncthreads();
    }

    #pragma unroll
    for (int e = 0; e < N_EXP; e++) {
        #pragma unroll
        for (int off = 16; off > 0; off >>= 1) {
            acc0[e] += __shfl_xor_sync(0xffffffffu, acc0[e], off);
            acc1[e] += __shfl_xor_sync(0xffffffffu, acc1[e], off);
        }
    }

    if (lane == 0) {
        float* gate = out + (size_t)N_TOK * N_EXP * CAP;
        float* idxf = gate + N_TOK * TOPK;
        #pragma unroll
        for (int t = 0; t < 2; t++) {
            float* a = t ? acc1 : acc0;
            int tok = t0 + t;
            float best = -INFINITY, sec = -INFINITY;
            int bi = 0, si = 0;
            #pragma unroll
            for (int e = 0; e < N_EXP; e++) {
                float v = a[e];
                if (v > best)     { sec = best; si = bi; best = v; bi = e; }
                else if (v > sec) { sec = v;    si = e; }
            }
            float g0 = 1.0f / (1.0f + expf(sec - best));
            gate[tok * 2 + 0] = g0;
            gate[tok * 2 + 1] = 1.0f - g0;
            idxf[tok * 2 + 0] = (float)bi;
            idxf[tok * 2 + 1] = (float)si;
            g_choice[tok * 2 + 0] = bi;
            g_choice[tok * 2 + 1] = si;
        }
    }
}

// ---------------------------------------------------------------------------
// Scan + scatter: per-(k,expert) prefix over 4096 tokens, writes 1.0f into
// the (already zeroed) dispatcher. 16 blocks, 1024 threads, 4 tokens/thread.
// ---------------------------------------------------------------------------
__global__ void k_scan_scatter(float* __restrict__ out) {
    int k = blockIdx.x >> 3;
    int e = blockIdx.x & 7;
    int tid  = threadIdx.x;
    int lane = tid & 31;
    int wid  = tid >> 5;

    __shared__ int warp_sums[32];

    int n0 = tid * 4;
    int flags[4];
    int localex[4];
    int s = 0;
    #pragma unroll
    for (int j = 0; j < 4; j++) {
        flags[j]   = (g_choice[(n0 + j) * 2 + k] == e) ? 1 : 0;
        localex[j] = s;
        s += flags[j];
    }

    int inc = s;
    #pragma unroll
    for (int off = 1; off < 32; off <<= 1) {
        int v = __shfl_up_sync(0xffffffffu, inc, off);
        if (lane >= off) inc += v;
    }
    if (lane == 31) warp_sums[wid] = inc;
    __syncthreads();

    if (wid == 0) {
        int v = warp_sums[lane];
        int winc = v;
        #pragma unroll
        for (int off = 1; off < 32; off <<= 1) {
            int u = __shfl_up_sync(0xffffffffu, winc, off);
            if (lane >= off) winc += u;
        }
        warp_sums[lane] = winc - v;
    }
    __syncthreads();

    int thread_prefix = warp_sums[wid] + (inc - s);

    #pragma unroll
    for (int j = 0; j < 4; j++) {
        if (flags[j]) {
            int pri = thread_prefix + localex[j] + 1;
            if (pri <= CAP)
                out[(size_t)(n0 + j) * (N_EXP * CAP) + e * CAP + (pri - 1)] = 1.0f;
        }
    }
}

// ---------------------------------------------------------------------------
// Fork-join: memset (64 MB zero of dispatcher) runs on a side stream in
// parallel with the GEMM on the main stream; scan+scatter joins both.
// Stream/events created once on the first (non-captured) correctness call.
// ---------------------------------------------------------------------------
static cudaStream_t s_side = 0;
static cudaEvent_t  s_fork = 0, s_join = 0;
static bool s_init = false;

extern "C" void kernel_launch(void* const* d_in, const int* in_sizes, int n_in,
                              void* d_out, int out_size) {
    const float* x = (const float*)d_in[0];   // [4096, 2048]
    const float* W = (const float*)d_in[1];   // [2048, 8]
    float* out = (float*)d_out;

    if (!s_init) {
        cudaStreamCreateWithFlags(&s_side, cudaStreamNonBlocking);
        cudaEventCreateWithFlags(&s_fork, cudaEventDisableTiming);
        cudaEventCreateWithFlags(&s_join, cudaEventDisableTiming);
        s_init = true;
    }

    // fork side stream off the (possibly capturing) main stream
    cudaEventRecord(s_fork, 0);
    cudaStreamWaitEvent(s_side, s_fork, 0);

    // branch A: zero the dispatcher (write stream)
    cudaMemsetAsync(out, 0, DISP_BYTES, s_side);
    cudaEventRecord(s_join, s_side);

    // branch B: GEMM + top-2 + softmax (read stream)
    k_logits_topk<<<256, 256>>>(x, W, out);

    // join, then scatter the ones
    cudaStreamWaitEvent(0, s_join, 0);
    k_scan_scatter<<<16, 1024>>>(out);
}